// round 6
// baseline (speedup 1.0000x reference)
#include <cuda_runtime.h>
#include <cuda_bf16.h>
#include <stdint.h>
#include <cstdint>
#include <math.h>

// Problem constants
#define NN   50000
#define EE   800000
#define IN_D 256
#define HC   256
#define HH   4
#define CC   64
#define LAT  32
#define MT   391          // ceil(50000/128)

// ---------------- device scratch ------------------------------------------
__device__ float g_xl[NN * HC];
__device__ float g_xr[NN * HC];
__device__ float g_h [NN * CC];
__device__ uint32_t g_aph[MT * 128 * 256];   // A hi plane, fragment-permuted
__device__ uint32_t g_apl[MT * 128 * 256];   // A lo plane
__device__ uint32_t g_wph[4 * 65536];        // W hi planes, fragment-permuted
__device__ uint32_t g_wpl[4 * 65536];
__device__ int   g_deg [NN];
__device__ int   g_off [NN + 1];
__device__ int   g_fill[NN];
__device__ int   g_csr [EE];
__device__ int   g_bsum[64];
__device__ int   g_boff[64];

// ---------------- helpers ---------------------------------------------------
__device__ __forceinline__ uint32_t smem_u32(const void* p) {
    uint32_t a;
    asm("{ .reg .u64 t; cvta.to.shared.u64 t, %1; cvt.u32.u64 %0, t; }" : "=r"(a) : "l"(p));
    return a;
}
__device__ __forceinline__ uint32_t f2tf32(float x) {
    uint32_t r;
    asm("cvt.rna.tf32.f32 %0, %1;" : "=r"(r) : "f"(x));
    return r;
}
__device__ __forceinline__ void split_tf32(float v, uint32_t& hi, uint32_t& lo) {
    hi = f2tf32(v);
    lo = f2tf32(v - __uint_as_float(hi));
}
__device__ __forceinline__ void mma_tf32(float* c, const uint32_t* a, const uint32_t* b) {
    asm volatile(
        "mma.sync.aligned.m16n8k8.row.col.f32.tf32.tf32.f32 "
        "{%0,%1,%2,%3}, {%4,%5,%6,%7}, {%8,%9}, {%0,%1,%2,%3};"
        : "+f"(c[0]), "+f"(c[1]), "+f"(c[2]), "+f"(c[3])
        : "r"(a[0]), "r"(a[1]), "r"(a[2]), "r"(a[3]), "r"(b[0]), "r"(b[1]));
}
#define CP_ASYNC16(dst, src) \
    asm volatile("cp.async.ca.shared.global [%0], [%1], 16;" :: "r"((uint32_t)(dst)), "l"(src))
#define CP_COMMIT  asm volatile("cp.async.commit_group;" ::: "memory")
#define CP_WAIT(n) asm volatile("cp.async.wait_group %0;" :: "n"(n) : "memory")

// ---------------- graph preprocessing ---------------------------------------
__global__ void init_kernel() {
    int i = blockIdx.x * blockDim.x + threadIdx.x;
    if (i < NN) { g_deg[i] = 0; g_fill[i] = 0; }
}

__global__ void edge_deg_kernel(const int* __restrict__ dst) {
    int e = blockIdx.x * blockDim.x + threadIdx.x;
    if (e >= EE) return;
    atomicAdd(&g_deg[dst[e]], 1);
}

__global__ void deg_blocksum_kernel() {
    int i = blockIdx.x * 1024 + threadIdx.x;
    int v = (i < NN) ? g_deg[i] : 0;
    __shared__ int ws[32];
    int lane = threadIdx.x & 31, wid = threadIdx.x >> 5;
    #pragma unroll
    for (int o = 16; o > 0; o >>= 1) v += __shfl_down_sync(0xffffffff, v, o);
    if (lane == 0) ws[wid] = v;
    __syncthreads();
    if (wid == 0) {
        int s = ws[lane];
        #pragma unroll
        for (int o = 16; o > 0; o >>= 1) s += __shfl_down_sync(0xffffffff, s, o);
        if (lane == 0) g_bsum[blockIdx.x] = s;
    }
}

__global__ void bsum_scan_kernel(int nblk) {
    int run = 0;
    for (int i = 0; i < nblk; i++) { g_boff[i] = run; run += g_bsum[i]; }
    g_off[NN] = run;
}

__global__ void off_write_kernel() {
    __shared__ int s[1024];
    int t = threadIdx.x;
    int i = blockIdx.x * 1024 + t;
    int v = (i < NN) ? g_deg[i] : 0;
    s[t] = v;
    __syncthreads();
    #pragma unroll
    for (int o = 1; o < 1024; o <<= 1) {
        int u = (t >= o) ? s[t - o] : 0;
        __syncthreads();
        s[t] += u;
        __syncthreads();
    }
    if (i < NN) g_off[i] = g_boff[blockIdx.x] + s[t] - v;
}

__global__ void csr_fill_kernel(const int* __restrict__ dst) {
    int e = blockIdx.x * blockDim.x + threadIdx.x;
    if (e >= EE) return;
    int d = dst[e];
    int pos = g_off[d] + atomicAdd(&g_fill[d], 1);
    g_csr[pos] = e;
}

// ---------------- A conversion: fp32 row-major -> tf32 hi/lo fragment order --
// layout: [mt][kq][m16:8][lane:32][reg:4]
__global__ void convertA_kernel(const float* __restrict__ src, int K, int KQ) {
    int id = blockIdx.x * 256 + threadIdx.x;
    int total = MT * KQ * 256;
    if (id >= total) return;
    int lane = id & 31;
    int t = id >> 5;
    int m16 = t & 7; t >>= 3;
    int kq = t % KQ;
    int mt = t / KQ;
    int g = lane >> 2, tig = lane & 3;
    int row = mt * 128 + m16 * 16 + g;
    int col = kq * 8 + tig;
    float v0 = (row     < NN) ? src[(size_t)row * K + col]           : 0.f;
    float v1 = (row + 8 < NN) ? src[(size_t)(row + 8) * K + col]     : 0.f;
    float v2 = (row     < NN) ? src[(size_t)row * K + col + 4]       : 0.f;
    float v3 = (row + 8 < NN) ? src[(size_t)(row + 8) * K + col + 4] : 0.f;
    uint4 h, l;
    split_tf32(v0, h.x, l.x);
    split_tf32(v1, h.y, l.y);
    split_tf32(v2, h.z, l.z);
    split_tf32(v3, h.w, l.w);
    *(uint4*)(g_aph + (size_t)id * 4) = h;
    *(uint4*)(g_apl + (size_t)id * 4) = l;
}

// ---------------- W conversion: [K][256] -> tf32 hi/lo B-fragment order ------
// layout per widx: [kq][n8:32][lane:32][reg:2]
__global__ void convertW_kernel(const float* __restrict__ Wl0, const float* __restrict__ Wr0,
                                const float* __restrict__ Wl1, const float* __restrict__ Wr1) {
    int id = blockIdx.x * 256 + threadIdx.x;   // total 131072
    int widx = id >> 15;
    int rem = id & 32767;
    int kq = rem >> 10;
    int n8 = (rem >> 5) & 31;
    int lane = rem & 31;
    int KQw = (widx < 2) ? 32 : 8;
    if (kq >= KQw) return;
    const float* W = (widx == 0) ? Wl0 : (widx == 1) ? Wr0 : (widx == 2) ? Wl1 : Wr1;
    int g = lane >> 2, tig = lane & 3;
    int n = n8 * 8 + g;
    float v0 = W[(size_t)(kq * 8 + tig) * 256 + n];
    float v1 = W[(size_t)(kq * 8 + 4 + tig) * 256 + n];
    uint32_t h0, l0, h1, l1;
    split_tf32(v0, h0, l0);
    split_tf32(v1, h1, l1);
    int off = widx * 65536 + (kq * 2048 + n8 * 64 + lane * 2);
    g_wph[off] = h0; g_wph[off + 1] = h1;
    g_wpl[off] = l0; g_wpl[off + 1] = l1;
}

// ---------------- fused tf32 tensor GEMM: {xl,xr} = A @ {Wl,Wr} + bias -------
// BM=128, BN=128, BK=16, grid (MT, 4): y<2 -> left weights, y&1 -> col half.
// 3-stage cp.async pipeline, stage = 8192 u32 (32 KB): Ah 0, Al 2048, Bh 4096, Bl 6144.
__global__ __launch_bounds__(256, 2)
void gemm_fused_kernel(const uint32_t* __restrict__ aph, const uint32_t* __restrict__ apl,
                       const uint32_t* __restrict__ wLh, const uint32_t* __restrict__ wLl,
                       const uint32_t* __restrict__ wRh, const uint32_t* __restrict__ wRl,
                       const float* __restrict__ biasL, const float* __restrict__ biasR,
                       float* __restrict__ CL, float* __restrict__ CR, int KQ) {
    extern __shared__ uint32_t sm[];
    uint32_t sb = smem_u32(sm);
    const int tid = threadIdx.x, lane = tid & 31, wid = tid >> 5;
    const int wm = wid >> 1, wn = wid & 1;
    const int mt = blockIdx.x;
    const int ysel = blockIdx.y;
    const uint32_t* bph = (ysel < 2) ? wLh : wRh;
    const uint32_t* bpl = (ysel < 2) ? wLl : wRl;
    const float* bias   = (ysel < 2) ? biasL : biasR;
    float* C            = (ysel < 2) ? CL : CR;
    const int bn8 = (ysel & 1) * 16;
    const int nch = KQ >> 1;                 // BK=16 -> 2 kq per chunk

    const uint32_t* agh = aph + (size_t)mt * KQ * 1024;
    const uint32_t* agl = apl + (size_t)mt * KQ * 1024;

    float acc[2][8][4];
    #pragma unroll
    for (int mi = 0; mi < 2; mi++)
        #pragma unroll
        for (int ni = 0; ni < 8; ni++)
            #pragma unroll
            for (int r = 0; r < 4; r++) acc[mi][ni][r] = 0.f;

    auto load_chunk = [&](int ch, int s) {
        uint32_t base = sb + s * 32768;      // bytes (8192 u32)
        #pragma unroll
        for (int i = 0; i < 2; i++) {
            int kq = ch * 2 + i;
            CP_ASYNC16(base + (i * 1024 + tid * 4) * 4,          agh + kq * 1024 + tid * 4);
            CP_ASYNC16(base + (2048 + i * 1024 + tid * 4) * 4,   agl + kq * 1024 + tid * 4);
            CP_ASYNC16(base + (4096 + i * 1024 + tid * 4) * 4,   bph + kq * 2048 + bn8 * 64 + tid * 4);
            CP_ASYNC16(base + (6144 + i * 1024 + tid * 4) * 4,   bpl + kq * 2048 + bn8 * 64 + tid * 4);
        }
        CP_COMMIT;
    };

    load_chunk(0, 0);
    load_chunk(1, 1);

    for (int ch = 0; ch < nch; ch++) {
        if (ch + 1 < nch) { CP_WAIT(1); } else { CP_WAIT(0); }
        __syncthreads();
        if (ch + 2 < nch) load_chunk(ch + 2, (ch + 2) % 3);

        const uint32_t* st = sm + (ch % 3) * 8192;
        #pragma unroll
        for (int i = 0; i < 2; i++) {
            uint32_t ah[2][4], al[2][4];
            #pragma unroll
            for (int mi = 0; mi < 2; mi++) {
                int m16 = wm * 2 + mi;
                uint4 vh = *(const uint4*)(st + i * 1024 + m16 * 128 + lane * 4);
                uint4 vl = *(const uint4*)(st + 2048 + i * 1024 + m16 * 128 + lane * 4);
                ah[mi][0] = vh.x; ah[mi][1] = vh.y; ah[mi][2] = vh.z; ah[mi][3] = vh.w;
                al[mi][0] = vl.x; al[mi][1] = vl.y; al[mi][2] = vl.z; al[mi][3] = vl.w;
            }
            #pragma unroll
            for (int ni = 0; ni < 8; ni++) {
                int n8l = wn * 8 + ni;
                uint2 bhv = *(const uint2*)(st + 4096 + i * 1024 + n8l * 64 + lane * 2);
                uint2 blv = *(const uint2*)(st + 6144 + i * 1024 + n8l * 64 + lane * 2);
                uint32_t bh[2] = {bhv.x, bhv.y}, bl[2] = {blv.x, blv.y};
                #pragma unroll
                for (int mi = 0; mi < 2; mi++) {
                    mma_tf32(acc[mi][ni], al[mi], bh);
                    mma_tf32(acc[mi][ni], ah[mi], bl);
                    mma_tf32(acc[mi][ni], ah[mi], bh);
                }
            }
        }
        __syncthreads();
    }

    // epilogue
    const int g = lane >> 2, tig = lane & 3;
    #pragma unroll
    for (int mi = 0; mi < 2; mi++) {
        int row = mt * 128 + wm * 32 + mi * 16 + g;
        #pragma unroll
        for (int ni = 0; ni < 8; ni++) {
            int col = (ysel & 1) * 128 + wn * 64 + ni * 8 + tig * 2;
            float b0 = __ldg(bias + col), b1 = __ldg(bias + col + 1);
            if (row < NN)
                *(float2*)(C + (size_t)row * 256 + col) =
                    make_float2(acc[mi][ni][0] + b0, acc[mi][ni][1] + b1);
            if (row + 8 < NN)
                *(float2*)(C + (size_t)(row + 8) * 256 + col) =
                    make_float2(acc[mi][ni][2] + b0, acc[mi][ni][3] + b1);
        }
    }
}

// ---------------- GATv2 aggregation: one warp per dst node ------------------
// 2 edges per iteration, two independent online-softmax states, merged at end.
__global__ __launch_bounds__(256)
void gat_agg_kernel(const float* __restrict__ xl, const float* __restrict__ xr,
                    const float* __restrict__ edge_attr,
                    const int* __restrict__ srcarr,
                    const float* __restrict__ We, const float* __restrict__ att,
                    const float* __restrict__ bias, float* __restrict__ out) {
    int warp = (blockIdx.x * blockDim.x + threadIdx.x) >> 5;
    if (warp >= NN) return;
    int lane  = threadIdx.x & 31;
    int node  = warp;
    int jbase = lane * 8;

    float we0[8], we1[8], we2[8], attv[8], xrv[8];
    #pragma unroll
    for (int i = 0; i < 8; i++) {
        int j = jbase + i;
        we0[i]  = We[j];
        we1[i]  = We[256 + j];
        we2[i]  = We[512 + j];
        attv[i] = att[j];
        xrv[i]  = xr[(size_t)node * HC + j];
    }

    float mx0 = -1e30f, d0 = 0.f, mx1 = -1e30f, d1 = 0.f;
    float acc0[8] = {}, acc1[8] = {};
    float sea0 = 0.f, sea1 = 0.f, sea2 = 0.f;
    int e0 = g_off[node], e1 = g_off[node + 1];

    // per-edge update on a given state
    auto update = [&](float& mx, float& dn, float* acc, const float* xlv,
                      float ea0, float ea1, float ea2) {
        float part = 0.f;
        #pragma unroll
        for (int i = 0; i < 8; i++) {
            float m = xlv[i] + xrv[i] + ea0 * we0[i] + ea1 * we1[i] + ea2 * we2[i];
            m = (m > 0.f) ? m : 0.2f * m;
            part += m * attv[i];
        }
        part += __shfl_xor_sync(0xffffffff, part, 1);
        part += __shfl_xor_sync(0xffffffff, part, 2);
        part += __shfl_xor_sync(0xffffffff, part, 4);
        float nm = fmaxf(mx, part);
        float sc = __expf(mx - nm);
        float pw = __expf(part - nm);
        dn = dn * sc + pw;
        #pragma unroll
        for (int i = 0; i < 8; i++) acc[i] = acc[i] * sc + pw * xlv[i];
        mx = nm;
    };

    int t = e0;
    for (; t + 1 < e1; t += 2) {
        int eA = g_csr[t], eB = g_csr[t + 1];
        int sA = srcarr[eA], sB = srcarr[eB];
        float a0 = edge_attr[eA * 3 + 0], a1 = edge_attr[eA * 3 + 1], a2 = edge_attr[eA * 3 + 2];
        float b0 = edge_attr[eB * 3 + 0], b1 = edge_attr[eB * 3 + 1], b2 = edge_attr[eB * 3 + 2];
        sea0 += a0 + b0; sea1 += a1 + b1; sea2 += a2 + b2;
        const float4* pA = (const float4*)(xl + (size_t)sA * HC + jbase);
        const float4* pB = (const float4*)(xl + (size_t)sB * HC + jbase);
        float4 vA0 = pA[0], vA1 = pA[1], vB0 = pB[0], vB1 = pB[1];
        float xlvA[8] = {vA0.x, vA0.y, vA0.z, vA0.w, vA1.x, vA1.y, vA1.z, vA1.w};
        float xlvB[8] = {vB0.x, vB0.y, vB0.z, vB0.w, vB1.x, vB1.y, vB1.z, vB1.w};
        update(mx0, d0, acc0, xlvA, a0, a1, a2);
        update(mx1, d1, acc1, xlvB, b0, b1, b2);
    }
    if (t < e1) {
        int eA = g_csr[t];
        int sA = srcarr[eA];
        float a0 = edge_attr[eA * 3 + 0], a1 = edge_attr[eA * 3 + 1], a2 = edge_attr[eA * 3 + 2];
        sea0 += a0; sea1 += a1; sea2 += a2;
        const float4* pA = (const float4*)(xl + (size_t)sA * HC + jbase);
        float4 vA0 = pA[0], vA1 = pA[1];
        float xlvA[8] = {vA0.x, vA0.y, vA0.z, vA0.w, vA1.x, vA1.y, vA1.z, vA1.w};
        update(mx0, d0, acc0, xlvA, a0, a1, a2);
    }

    // merge state1 into state0
    {
        float m = fmaxf(mx0, mx1);
        float s0 = __expf(mx0 - m), s1 = __expf(mx1 - m);
        d0 = d0 * s0 + d1 * s1;
        #pragma unroll
        for (int i = 0; i < 8; i++) acc0[i] = acc0[i] * s0 + acc1[i] * s1;
        mx0 = m;
    }

    // self loop (edge_attr = mean of incoming)
    {
        float inv = 1.f / fmaxf((float)(e1 - e0), 1.f);
        const float4* p = (const float4*)(xl + (size_t)node * HC + jbase);
        float4 v0 = p[0], v1 = p[1];
        float xlv[8] = {v0.x, v0.y, v0.z, v0.w, v1.x, v1.y, v1.z, v1.w};
        update(mx0, d0, acc0, xlv, sea0 * inv, sea1 * inv, sea2 * inv);
    }

    float inv = 1.f / d0;
    #pragma unroll
    for (int i = 0; i < 8; i++) {
        float r = acc0[i] * inv;
        r += __shfl_xor_sync(0xffffffff, r, 8);
        r += __shfl_xor_sync(0xffffffff, r, 16);
        acc0[i] = r * 0.25f;
    }
    if (lane < 8) {
        #pragma unroll
        for (int i = 0; i < 8; i++) {
            int c = jbase + i;
            out[(size_t)node * CC + c] = fmaxf(acc0[i] + bias[c], 0.f);
        }
    }
}

// ---------------- final projection ------------------------------------------
__global__ __launch_bounds__(256)
void mu_kernel(const float* __restrict__ h, const float* __restrict__ Wmu,
               const float* __restrict__ bmu, float* __restrict__ out) {
    __shared__ float sW[CC * LAT];
    __shared__ float sb[LAT];
    int tid = threadIdx.x;
    for (int i = tid; i < CC * LAT; i += 256) sW[i] = Wmu[i];
    if (tid < LAT) sb[tid] = bmu[tid];
    __syncthreads();
    int warp = tid >> 5, lane = tid & 31;
    int node = blockIdx.x * 8 + warp;
    if (node >= NN) return;
    const float* hr = h + (size_t)node * CC;
    float sum = sb[lane];
    #pragma unroll
    for (int c = 0; c < CC; c++)
        sum += hr[c] * sW[c * LAT + lane];
    out[(size_t)node * LAT + lane] = sum;
}

// ---------------- host launcher ---------------------------------------------
extern "C" void kernel_launch(void* const* d_in, const int* in_sizes, int n_in,
                              void* d_out, int out_size) {
    const float* x   = (const float*)d_in[0];
    const int*   ei  = (const int*)  d_in[1];
    const float* ea  = (const float*)d_in[2];
    const float* Wl0 = (const float*)d_in[3];
    const float* bl0 = (const float*)d_in[4];
    const float* Wr0 = (const float*)d_in[5];
    const float* br0 = (const float*)d_in[6];
    const float* We0 = (const float*)d_in[7];
    const float* at0 = (const float*)d_in[8];
    const float* bi0 = (const float*)d_in[9];
    const float* Wl1 = (const float*)d_in[10];
    const float* bl1 = (const float*)d_in[11];
    const float* Wr1 = (const float*)d_in[12];
    const float* br1 = (const float*)d_in[13];
    const float* We1 = (const float*)d_in[14];
    const float* at1 = (const float*)d_in[15];
    const float* bi1 = (const float*)d_in[16];
    const float* Wmu = (const float*)d_in[17];
    const float* bmu = (const float*)d_in[18];
    float* out = (float*)d_out;

    const int* src = ei;
    const int* dst = ei + EE;

    float* xl; cudaGetSymbolAddress((void**)&xl, g_xl);
    float* xr; cudaGetSymbolAddress((void**)&xr, g_xr);
    float* h ; cudaGetSymbolAddress((void**)&h , g_h );
    uint32_t* aph; cudaGetSymbolAddress((void**)&aph, g_aph);
    uint32_t* apl; cudaGetSymbolAddress((void**)&apl, g_apl);
    uint32_t* wph; cudaGetSymbolAddress((void**)&wph, g_wph);
    uint32_t* wpl; cudaGetSymbolAddress((void**)&wpl, g_wpl);

    cudaFuncSetAttribute(gemm_fused_kernel, cudaFuncAttributeMaxDynamicSharedMemorySize, 98304);

    const int SCAN_BLOCKS = (NN + 1023) / 1024;
    dim3 gemm_grid(MT, 4);
    dim3 agg_grid((NN + 7) / 8);

    // launch #3 = fused gemm L0 (ncu capture target)
    init_kernel<<<(NN + 255) / 256, 256>>>();
    convertA_kernel<<<(MT * 32 * 256 + 255) / 256, 256>>>(x, 256, 32);
    convertW_kernel<<<131072 / 256, 256>>>(Wl0, Wr0, Wl1, Wr1);

    gemm_fused_kernel<<<gemm_grid, 256, 98304>>>(aph, apl,
        wph + 0 * 65536, wpl + 0 * 65536, wph + 1 * 65536, wpl + 1 * 65536,
        bl0, br0, xl, xr, 32);

    edge_deg_kernel<<<(EE + 255) / 256, 256>>>(dst);
    deg_blocksum_kernel<<<SCAN_BLOCKS, 1024>>>();
    bsum_scan_kernel<<<1, 1>>>(SCAN_BLOCKS);
    off_write_kernel<<<SCAN_BLOCKS, 1024>>>();
    csr_fill_kernel<<<(EE + 255) / 256, 256>>>(dst);

    gat_agg_kernel<<<agg_grid, 256>>>(xl, xr, ea, src, We0, at0, bi0, h);

    convertA_kernel<<<(MT * 8 * 256 + 255) / 256, 256>>>(h, 64, 8);
    gemm_fused_kernel<<<gemm_grid, 256, 98304>>>(aph, apl,
        wph + 2 * 65536, wpl + 2 * 65536, wph + 3 * 65536, wpl + 3 * 65536,
        bl1, br1, xl, xr, 8);

    gat_agg_kernel<<<agg_grid, 256>>>(xl, xr, ea, src, We1, at1, bi1, h);

    mu_kernel<<<(NN + 7) / 8, 256>>>(h, Wmu, bmu, out);
}

// round 7
// speedup vs baseline: 1.3417x; 1.3417x over previous
#include <cuda_runtime.h>
#include <cuda_bf16.h>
#include <stdint.h>
#include <cstdint>
#include <math.h>

// Problem constants
#define NN   50000
#define EE   800000
#define IN_D 256
#define HC   256
#define HH   4
#define CC   64
#define LAT  32
#define MT   391          // ceil(50000/128)

// ---------------- device scratch ------------------------------------------
__device__ float g_xl[NN * HC];
__device__ float g_xr[NN * HC];
__device__ float g_h [NN * CC];
__device__ uint32_t g_aph[MT * 16 * 1024];   // A hi plane, bf16x2 fragment-permuted (25.6MB)
__device__ uint32_t g_apl[MT * 16 * 1024];   // A lo plane
__device__ uint32_t g_wph[4 * 32768];        // W hi planes, fragment-permuted
__device__ uint32_t g_wpl[4 * 32768];
__device__ int    g_deg [NN];
__device__ int    g_off [NN + 1];
__device__ int    g_fill[NN];
__device__ int    g_srccsr[EE];              // src node per CSR slot
__device__ float4 g_eacsr[EE];               // edge_attr per CSR slot (xyz used)
__device__ int    g_bsum[64];
__device__ int    g_boff[64];

// ---------------- helpers ---------------------------------------------------
__device__ __forceinline__ uint32_t smem_u32(const void* p) {
    uint32_t a;
    asm("{ .reg .u64 t; cvta.to.shared.u64 t, %1; cvt.u32.u64 %0, t; }" : "=r"(a) : "l"(p));
    return a;
}
__device__ __forceinline__ float tobf(float v) {
    return __bfloat162float(__float2bfloat16(v));
}
__device__ __forceinline__ uint32_t packbf(float a, float b) {
    __nv_bfloat162 v = __floats2bfloat162_rn(a, b);
    return *reinterpret_cast<uint32_t*>(&v);
}
__device__ __forceinline__ void mma_bf16(float* c, const uint32_t* a, const uint32_t* b) {
    asm volatile(
        "mma.sync.aligned.m16n8k16.row.col.f32.bf16.bf16.f32 "
        "{%0,%1,%2,%3}, {%4,%5,%6,%7}, {%8,%9}, {%0,%1,%2,%3};"
        : "+f"(c[0]), "+f"(c[1]), "+f"(c[2]), "+f"(c[3])
        : "r"(a[0]), "r"(a[1]), "r"(a[2]), "r"(a[3]), "r"(b[0]), "r"(b[1]));
}
#define CP_ASYNC16(dst, src) \
    asm volatile("cp.async.ca.shared.global [%0], [%1], 16;" :: "r"((uint32_t)(dst)), "l"(src))
#define CP_COMMIT  asm volatile("cp.async.commit_group;" ::: "memory")
#define CP_WAIT(n) asm volatile("cp.async.wait_group %0;" :: "n"(n) : "memory")

// ---------------- graph preprocessing ---------------------------------------
__global__ void init_kernel() {
    int i = blockIdx.x * blockDim.x + threadIdx.x;
    if (i < NN) { g_deg[i] = 0; g_fill[i] = 0; }
}

__global__ void edge_deg_kernel(const int* __restrict__ dst) {
    int e = blockIdx.x * blockDim.x + threadIdx.x;
    if (e >= EE) return;
    atomicAdd(&g_deg[dst[e]], 1);
}

__global__ void deg_blocksum_kernel() {
    int i = blockIdx.x * 1024 + threadIdx.x;
    int v = (i < NN) ? g_deg[i] : 0;
    __shared__ int ws[32];
    int lane = threadIdx.x & 31, wid = threadIdx.x >> 5;
    #pragma unroll
    for (int o = 16; o > 0; o >>= 1) v += __shfl_down_sync(0xffffffff, v, o);
    if (lane == 0) ws[wid] = v;
    __syncthreads();
    if (wid == 0) {
        int s = ws[lane];
        #pragma unroll
        for (int o = 16; o > 0; o >>= 1) s += __shfl_down_sync(0xffffffff, s, o);
        if (lane == 0) g_bsum[blockIdx.x] = s;
    }
}

__global__ void bsum_scan_kernel(int nblk) {
    int run = 0;
    for (int i = 0; i < nblk; i++) { g_boff[i] = run; run += g_bsum[i]; }
    g_off[NN] = run;
}

__global__ void off_write_kernel() {
    __shared__ int s[1024];
    int t = threadIdx.x;
    int i = blockIdx.x * 1024 + t;
    int v = (i < NN) ? g_deg[i] : 0;
    s[t] = v;
    __syncthreads();
    #pragma unroll
    for (int o = 1; o < 1024; o <<= 1) {
        int u = (t >= o) ? s[t - o] : 0;
        __syncthreads();
        s[t] += u;
        __syncthreads();
    }
    if (i < NN) g_off[i] = g_boff[blockIdx.x] + s[t] - v;
}

// fill CSR with src id + edge attrs directly (removes one indirection in agg)
__global__ void csr_fill_kernel(const int* __restrict__ src, const int* __restrict__ dst,
                                const float* __restrict__ ea) {
    int e = blockIdx.x * blockDim.x + threadIdx.x;
    if (e >= EE) return;
    int d = dst[e];
    int pos = g_off[d] + atomicAdd(&g_fill[d], 1);
    g_srccsr[pos] = src[e];
    g_eacsr[pos] = make_float4(ea[e * 3 + 0], ea[e * 3 + 1], ea[e * 3 + 2], 0.f);
}

// ---------------- A conversion: fp32 -> bf16 hi/lo, m16n8k16 fragment order --
// layout: [mt][kq16][m16:8][lane:32][reg:4 u32 (bf16x2)]
__global__ void convertA_kernel(const float* __restrict__ src, int K, int KQ) {
    int id = blockIdx.x * 256 + threadIdx.x;
    int total = MT * KQ * 256;
    if (id >= total) return;
    int lane = id & 31;
    int t = id >> 5;
    int m16 = t & 7; t >>= 3;
    int kq = t % KQ;
    int mt = t / KQ;
    int g = lane >> 2, tig = lane & 3;
    int row0 = mt * 128 + m16 * 16 + g, row1 = row0 + 8;
    int k0 = kq * 16 + tig * 2, k1 = k0 + 8;

    float a00 = (row0 < NN) ? src[(size_t)row0 * K + k0]     : 0.f;
    float a01 = (row0 < NN) ? src[(size_t)row0 * K + k0 + 1] : 0.f;
    float a10 = (row1 < NN) ? src[(size_t)row1 * K + k0]     : 0.f;
    float a11 = (row1 < NN) ? src[(size_t)row1 * K + k0 + 1] : 0.f;
    float a02 = (row0 < NN) ? src[(size_t)row0 * K + k1]     : 0.f;
    float a03 = (row0 < NN) ? src[(size_t)row0 * K + k1 + 1] : 0.f;
    float a12 = (row1 < NN) ? src[(size_t)row1 * K + k1]     : 0.f;
    float a13 = (row1 < NN) ? src[(size_t)row1 * K + k1 + 1] : 0.f;

    float h00 = tobf(a00), h01 = tobf(a01), h10 = tobf(a10), h11 = tobf(a11);
    float h02 = tobf(a02), h03 = tobf(a03), h12 = tobf(a12), h13 = tobf(a13);
    uint4 hi, lo;
    hi.x = packbf(h00, h01); lo.x = packbf(a00 - h00, a01 - h01);
    hi.y = packbf(h10, h11); lo.y = packbf(a10 - h10, a11 - h11);
    hi.z = packbf(h02, h03); lo.z = packbf(a02 - h02, a03 - h03);
    hi.w = packbf(h12, h13); lo.w = packbf(a12 - h12, a13 - h13);
    *(uint4*)(g_aph + (size_t)id * 4) = hi;
    *(uint4*)(g_apl + (size_t)id * 4) = lo;
}

// ---------------- W conversion: [K][256] -> bf16 hi/lo B-fragment order ------
// layout per widx: [kq16][n8:32][lane:32][reg:2 u32 (bf16x2 along k)]
__global__ void convertW_kernel(const float* __restrict__ Wl0, const float* __restrict__ Wr0,
                                const float* __restrict__ Wl1, const float* __restrict__ Wr1) {
    int id = blockIdx.x * 256 + threadIdx.x;   // total 65536
    int widx = id >> 14;
    int rem = id & 16383;
    int kq = rem >> 10;
    int n8 = (rem >> 5) & 31;
    int lane = rem & 31;
    int KQw = (widx < 2) ? 16 : 4;
    if (kq >= KQw) return;
    const float* W = (widx == 0) ? Wl0 : (widx == 1) ? Wr0 : (widx == 2) ? Wl1 : Wr1;
    int g = lane >> 2, tig = lane & 3;
    int n = n8 * 8 + g;
    int kb = kq * 16;
    float v0 = W[(size_t)(kb + 2 * tig) * 256 + n];
    float v1 = W[(size_t)(kb + 2 * tig + 1) * 256 + n];
    float v2 = W[(size_t)(kb + 2 * tig + 8) * 256 + n];
    float v3 = W[(size_t)(kb + 2 * tig + 9) * 256 + n];
    float h0 = tobf(v0), h1 = tobf(v1), h2 = tobf(v2), h3 = tobf(v3);
    int off = widx * 32768 + kq * 2048 + n8 * 64 + lane * 2;
    g_wph[off] = packbf(h0, h1); g_wph[off + 1] = packbf(h2, h3);
    g_wpl[off] = packbf(v0 - h0, v1 - h1); g_wpl[off + 1] = packbf(v2 - h2, v3 - h3);
}

// ---------------- fused bf16 3-term tensor GEMM ------------------------------
// {xl,xr}[M,256] = A[M,K] @ {Wl,Wr} + bias.  BM=128, BN=128, BK=32 (2 k16 steps),
// grid (MT, 4): y<2 -> left weights, y&1 -> column half. 3-stage cp.async pipeline,
// stage = 8192 u32 (32KB): Ah 0, Al 2048, Bh 4096, Bl 6144.
__global__ __launch_bounds__(256, 2)
void gemm_fused_kernel(const uint32_t* __restrict__ aph, const uint32_t* __restrict__ apl,
                       const uint32_t* __restrict__ wLh, const uint32_t* __restrict__ wLl,
                       const uint32_t* __restrict__ wRh, const uint32_t* __restrict__ wRl,
                       const float* __restrict__ biasL, const float* __restrict__ biasR,
                       float* __restrict__ CL, float* __restrict__ CR, int KQ) {
    extern __shared__ uint32_t sm[];
    uint32_t sb = smem_u32(sm);
    const int tid = threadIdx.x, lane = tid & 31, wid = tid >> 5;
    const int wm = wid >> 1, wn = wid & 1;
    const int mt = blockIdx.x;
    const int ysel = blockIdx.y;
    const uint32_t* bph = (ysel < 2) ? wLh : wRh;
    const uint32_t* bpl = (ysel < 2) ? wLl : wRl;
    const float* bias   = (ysel < 2) ? biasL : biasR;
    float* C            = (ysel < 2) ? CL : CR;
    const int bn8 = (ysel & 1) * 16;
    const int nch = KQ >> 1;                 // 2 k16 steps per chunk

    const uint32_t* agh = aph + (size_t)mt * KQ * 1024;
    const uint32_t* agl = apl + (size_t)mt * KQ * 1024;

    float acc[2][8][4];
    #pragma unroll
    for (int mi = 0; mi < 2; mi++)
        #pragma unroll
        for (int ni = 0; ni < 8; ni++)
            #pragma unroll
            for (int r = 0; r < 4; r++) acc[mi][ni][r] = 0.f;

    auto load_chunk = [&](int ch, int s) {
        uint32_t base = sb + s * 32768;      // bytes
        #pragma unroll
        for (int i = 0; i < 2; i++) {
            int kq = ch * 2 + i;
            CP_ASYNC16(base + (i * 1024 + tid * 4) * 4,          agh + kq * 1024 + tid * 4);
            CP_ASYNC16(base + (2048 + i * 1024 + tid * 4) * 4,   agl + kq * 1024 + tid * 4);
            CP_ASYNC16(base + (4096 + i * 1024 + tid * 4) * 4,   bph + kq * 2048 + bn8 * 64 + tid * 4);
            CP_ASYNC16(base + (6144 + i * 1024 + tid * 4) * 4,   bpl + kq * 2048 + bn8 * 64 + tid * 4);
        }
        CP_COMMIT;
    };

    load_chunk(0, 0);
    if (nch > 1) load_chunk(1, 1);

    for (int ch = 0; ch < nch; ch++) {
        if (ch + 1 < nch) { CP_WAIT(1); } else { CP_WAIT(0); }
        __syncthreads();
        if (ch + 2 < nch) load_chunk(ch + 2, (ch + 2) % 3);

        const uint32_t* st = sm + (ch % 3) * 8192;
        #pragma unroll
        for (int i = 0; i < 2; i++) {
            uint32_t ah[2][4], al[2][4];
            #pragma unroll
            for (int mi = 0; mi < 2; mi++) {
                int m16 = wm * 2 + mi;
                uint4 vh = *(const uint4*)(st + i * 1024 + m16 * 128 + lane * 4);
                uint4 vl = *(const uint4*)(st + 2048 + i * 1024 + m16 * 128 + lane * 4);
                ah[mi][0] = vh.x; ah[mi][1] = vh.y; ah[mi][2] = vh.z; ah[mi][3] = vh.w;
                al[mi][0] = vl.x; al[mi][1] = vl.y; al[mi][2] = vl.z; al[mi][3] = vl.w;
            }
            #pragma unroll
            for (int ni = 0; ni < 8; ni++) {
                int n8l = wn * 8 + ni;
                uint2 bhv = *(const uint2*)(st + 4096 + i * 1024 + n8l * 64 + lane * 2);
                uint2 blv = *(const uint2*)(st + 6144 + i * 1024 + n8l * 64 + lane * 2);
                uint32_t bh[2] = {bhv.x, bhv.y}, bl[2] = {blv.x, blv.y};
                #pragma unroll
                for (int mi = 0; mi < 2; mi++) {
                    mma_bf16(acc[mi][ni], al[mi], bh);
                    mma_bf16(acc[mi][ni], ah[mi], bl);
                    mma_bf16(acc[mi][ni], ah[mi], bh);
                }
            }
        }
        __syncthreads();
    }

    // epilogue
    const int g = lane >> 2, tig = lane & 3;
    #pragma unroll
    for (int mi = 0; mi < 2; mi++) {
        int row = mt * 128 + wm * 32 + mi * 16 + g;
        #pragma unroll
        for (int ni = 0; ni < 8; ni++) {
            int col = (ysel & 1) * 128 + wn * 64 + ni * 8 + tig * 2;
            float b0 = __ldg(bias + col), b1 = __ldg(bias + col + 1);
            if (row < NN)
                *(float2*)(C + (size_t)row * 256 + col) =
                    make_float2(acc[mi][ni][0] + b0, acc[mi][ni][1] + b1);
            if (row + 8 < NN)
                *(float2*)(C + (size_t)(row + 8) * 256 + col) =
                    make_float2(acc[mi][ni][2] + b0, acc[mi][ni][3] + b1);
        }
    }
}

// ---------------- GATv2 aggregation: warp per dst node, software pipelined ---
__global__ __launch_bounds__(256)
void gat_agg_kernel(const float* __restrict__ xl, const float* __restrict__ xr,
                    const float* __restrict__ We, const float* __restrict__ att,
                    const float* __restrict__ bias, float* __restrict__ out) {
    int warp = (blockIdx.x * blockDim.x + threadIdx.x) >> 5;
    if (warp >= NN) return;
    int lane  = threadIdx.x & 31;
    int node  = warp;
    int jbase = lane * 8;

    float we0[8], we1[8], we2[8], attv[8], xrv[8];
    #pragma unroll
    for (int i = 0; i < 8; i++) {
        int j = jbase + i;
        we0[i]  = We[j];
        we1[i]  = We[256 + j];
        we2[i]  = We[512 + j];
        attv[i] = att[j];
        xrv[i]  = xr[(size_t)node * HC + j];
    }

    float mx = -1e30f, den = 0.f;
    float acc[8] = {};
    float sea0 = 0.f, sea1 = 0.f, sea2 = 0.f;
    int e0 = g_off[node], e1 = g_off[node + 1];

    auto update = [&](const float* xlv, float ea0, float ea1, float ea2) {
        float part = 0.f;
        #pragma unroll
        for (int i = 0; i < 8; i++) {
            float m = xlv[i] + xrv[i] + ea0 * we0[i] + ea1 * we1[i] + ea2 * we2[i];
            m = (m > 0.f) ? m : 0.2f * m;
            part += m * attv[i];
        }
        part += __shfl_xor_sync(0xffffffff, part, 1);
        part += __shfl_xor_sync(0xffffffff, part, 2);
        part += __shfl_xor_sync(0xffffffff, part, 4);
        float nm = fmaxf(mx, part);
        float sc = __expf(mx - nm);
        float pw = __expf(part - nm);
        den = den * sc + pw;
        #pragma unroll
        for (int i = 0; i < 8; i++) acc[i] = acc[i] * sc + pw * xlv[i];
        mx = nm;
    };

    // software pipeline: src prefetched 2 ahead, xl row + ea prefetched 1 ahead
    int s1 = 0;
    float4 xa, xb, f0;
    if (e0 < e1) {
        int s0 = g_srccsr[e0];
        f0 = __ldg(&g_eacsr[e0]);
        const float4* p = (const float4*)(xl + (size_t)s0 * HC + jbase);
        xa = __ldg(p); xb = __ldg(p + 1);
        if (e0 + 1 < e1) s1 = g_srccsr[e0 + 1];
    }

    for (int t = e0; t < e1; t++) {
        float4 na, nb, f1;
        int s2 = 0;
        if (t + 1 < e1) {
            const float4* p = (const float4*)(xl + (size_t)s1 * HC + jbase);
            na = __ldg(p); nb = __ldg(p + 1);
            f1 = __ldg(&g_eacsr[t + 1]);
        }
        if (t + 2 < e1) s2 = g_srccsr[t + 2];

        sea0 += f0.x; sea1 += f0.y; sea2 += f0.z;
        float xlv[8] = {xa.x, xa.y, xa.z, xa.w, xb.x, xb.y, xb.z, xb.w};
        update(xlv, f0.x, f0.y, f0.z);

        xa = na; xb = nb; f0 = f1; s1 = s2;
    }

    // self loop (edge_attr = mean of incoming)
    {
        float inv = 1.f / fmaxf((float)(e1 - e0), 1.f);
        const float4* p = (const float4*)(xl + (size_t)node * HC + jbase);
        float4 v0 = __ldg(p), v1 = __ldg(p + 1);
        float xlv[8] = {v0.x, v0.y, v0.z, v0.w, v1.x, v1.y, v1.z, v1.w};
        update(xlv, sea0 * inv, sea1 * inv, sea2 * inv);
    }

    float inv = 1.f / den;
    #pragma unroll
    for (int i = 0; i < 8; i++) {
        float r = acc[i] * inv;
        r += __shfl_xor_sync(0xffffffff, r, 8);
        r += __shfl_xor_sync(0xffffffff, r, 16);
        acc[i] = r * 0.25f;
    }
    if (lane < 8) {
        #pragma unroll
        for (int i = 0; i < 8; i++) {
            int c = jbase + i;
            out[(size_t)node * CC + c] = fmaxf(acc[i] + bias[c], 0.f);
        }
    }
}

// ---------------- final projection ------------------------------------------
__global__ __launch_bounds__(256)
void mu_kernel(const float* __restrict__ h, const float* __restrict__ Wmu,
               const float* __restrict__ bmu, float* __restrict__ out) {
    __shared__ float sW[CC * LAT];
    __shared__ float sb[LAT];
    int tid = threadIdx.x;
    for (int i = tid; i < CC * LAT; i += 256) sW[i] = Wmu[i];
    if (tid < LAT) sb[tid] = bmu[tid];
    __syncthreads();
    int warp = tid >> 5, lane = tid & 31;
    int node = blockIdx.x * 8 + warp;
    if (node >= NN) return;
    const float* hr = h + (size_t)node * CC;
    float sum = sb[lane];
    #pragma unroll
    for (int c = 0; c < CC; c++)
        sum += hr[c] * sW[c * LAT + lane];
    out[(size_t)node * LAT + lane] = sum;
}

// ---------------- host launcher ---------------------------------------------
extern "C" void kernel_launch(void* const* d_in, const int* in_sizes, int n_in,
                              void* d_out, int out_size) {
    const float* x   = (const float*)d_in[0];
    const int*   ei  = (const int*)  d_in[1];
    const float* ea  = (const float*)d_in[2];
    const float* Wl0 = (const float*)d_in[3];
    const float* bl0 = (const float*)d_in[4];
    const float* Wr0 = (const float*)d_in[5];
    const float* br0 = (const float*)d_in[6];
    const float* We0 = (const float*)d_in[7];
    const float* at0 = (const float*)d_in[8];
    const float* bi0 = (const float*)d_in[9];
    const float* Wl1 = (const float*)d_in[10];
    const float* bl1 = (const float*)d_in[11];
    const float* Wr1 = (const float*)d_in[12];
    const float* br1 = (const float*)d_in[13];
    const float* We1 = (const float*)d_in[14];
    const float* at1 = (const float*)d_in[15];
    const float* bi1 = (const float*)d_in[16];
    const float* Wmu = (const float*)d_in[17];
    const float* bmu = (const float*)d_in[18];
    float* out = (float*)d_out;

    const int* src = ei;
    const int* dst = ei + EE;

    float* xl; cudaGetSymbolAddress((void**)&xl, g_xl);
    float* xr; cudaGetSymbolAddress((void**)&xr, g_xr);
    float* h ; cudaGetSymbolAddress((void**)&h , g_h );
    uint32_t* aph; cudaGetSymbolAddress((void**)&aph, g_aph);
    uint32_t* apl; cudaGetSymbolAddress((void**)&apl, g_apl);
    uint32_t* wph; cudaGetSymbolAddress((void**)&wph, g_wph);
    uint32_t* wpl; cudaGetSymbolAddress((void**)&wpl, g_wpl);

    cudaFuncSetAttribute(gemm_fused_kernel, cudaFuncAttributeMaxDynamicSharedMemorySize, 98304);

    const int SCAN_BLOCKS = (NN + 1023) / 1024;
    dim3 gemm_grid(MT, 4);
    dim3 agg_grid((NN + 7) / 8);

    // launch #3 = fused gemm L0 (ncu capture target)
    init_kernel<<<(NN + 255) / 256, 256>>>();
    convertA_kernel<<<(MT * 16 * 256 + 255) / 256, 256>>>(x, 256, 16);
    convertW_kernel<<<65536 / 256, 256>>>(Wl0, Wr0, Wl1, Wr1);

    gemm_fused_kernel<<<gemm_grid, 256, 98304>>>(aph, apl,
        wph + 0 * 32768, wpl + 0 * 32768, wph + 1 * 32768, wpl + 1 * 32768,
        bl0, br0, xl, xr, 16);

    edge_deg_kernel<<<(EE + 255) / 256, 256>>>(dst);
    deg_blocksum_kernel<<<SCAN_BLOCKS, 1024>>>();
    bsum_scan_kernel<<<1, 1>>>(SCAN_BLOCKS);
    off_write_kernel<<<SCAN_BLOCKS, 1024>>>();
    csr_fill_kernel<<<(EE + 255) / 256, 256>>>(src, dst, ea);

    gat_agg_kernel<<<agg_grid, 256>>>(xl, xr, We0, at0, bi0, h);

    convertA_kernel<<<(MT * 4 * 256 + 255) / 256, 256>>>(h, 64, 4);
    gemm_fused_kernel<<<gemm_grid, 256, 98304>>>(aph, apl,
        wph + 2 * 32768, wpl + 2 * 32768, wph + 3 * 32768, wpl + 3 * 32768,
        bl1, br1, xl, xr, 4);

    gat_agg_kernel<<<agg_grid, 256>>>(xl, xr, We1, at1, bi1, h);

    mu_kernel<<<(NN + 7) / 8, 256>>>(h, Wmu, bmu, out);
}

// round 8
// speedup vs baseline: 1.5445x; 1.1511x over previous
#include <cuda_runtime.h>
#include <cuda_bf16.h>
#include <stdint.h>
#include <cstdint>
#include <math.h>

// Problem constants
#define NN   50000
#define EE   800000
#define IN_D 256
#define HC   256
#define HH   4
#define CC   64
#define LAT  32
#define MT   391          // ceil(50000/128)

// ---------------- device scratch ------------------------------------------
__device__ float g_xl[NN * HC];
__device__ float g_xr[NN * HC];
__device__ float g_h [NN * CC];
__device__ uint32_t g_aph[MT * 16 * 1024];   // A hi plane, bf16x2 fragment-permuted
__device__ uint32_t g_apl[MT * 16 * 1024];   // A lo plane
__device__ uint32_t g_wph[4 * 32768];        // W hi planes, fragment-permuted
__device__ uint32_t g_wpl[4 * 32768];
__device__ int    g_deg [NN];
__device__ int    g_off [NN + 1];
__device__ int    g_fill[NN];
__device__ int    g_srccsr[EE];              // src node per CSR slot
__device__ float4 g_eacsr[EE];               // edge_attr per CSR slot (xyz used)
__device__ int    g_bsum[64];
__device__ int    g_boff[64];

// ---------------- helpers ---------------------------------------------------
__device__ __forceinline__ uint32_t smem_u32(const void* p) {
    uint32_t a;
    asm("{ .reg .u64 t; cvta.to.shared.u64 t, %1; cvt.u32.u64 %0, t; }" : "=r"(a) : "l"(p));
    return a;
}
__device__ __forceinline__ float tobf(float v) {
    return __bfloat162float(__float2bfloat16(v));
}
__device__ __forceinline__ uint32_t packbf(float a, float b) {
    __nv_bfloat162 v = __floats2bfloat162_rn(a, b);
    return *reinterpret_cast<uint32_t*>(&v);
}
__device__ __forceinline__ void mma_bf16(float* c, const uint32_t* a, const uint32_t* b) {
    asm volatile(
        "mma.sync.aligned.m16n8k16.row.col.f32.bf16.bf16.f32 "
        "{%0,%1,%2,%3}, {%4,%5,%6,%7}, {%8,%9}, {%0,%1,%2,%3};"
        : "+f"(c[0]), "+f"(c[1]), "+f"(c[2]), "+f"(c[3])
        : "r"(a[0]), "r"(a[1]), "r"(a[2]), "r"(a[3]), "r"(b[0]), "r"(b[1]));
}
#define CP_ASYNC16(dst, src) \
    asm volatile("cp.async.ca.shared.global [%0], [%1], 16;" :: "r"((uint32_t)(dst)), "l"(src))
#define CP_COMMIT  asm volatile("cp.async.commit_group;" ::: "memory")
#define CP_WAIT(n) asm volatile("cp.async.wait_group %0;" :: "n"(n) : "memory")

// ---------------- graph preprocessing ---------------------------------------
__global__ void init_kernel() {
    int i = blockIdx.x * blockDim.x + threadIdx.x;
    if (i < NN) { g_deg[i] = 0; g_fill[i] = 0; }
}

__global__ void edge_deg_kernel(const int* __restrict__ dst) {
    int e = blockIdx.x * blockDim.x + threadIdx.x;
    if (e >= EE) return;
    atomicAdd(&g_deg[dst[e]], 1);
}

__global__ void deg_blocksum_kernel() {
    int i = blockIdx.x * 1024 + threadIdx.x;
    int v = (i < NN) ? g_deg[i] : 0;
    __shared__ int ws[32];
    int lane = threadIdx.x & 31, wid = threadIdx.x >> 5;
    #pragma unroll
    for (int o = 16; o > 0; o >>= 1) v += __shfl_down_sync(0xffffffff, v, o);
    if (lane == 0) ws[wid] = v;
    __syncthreads();
    if (wid == 0) {
        int s = ws[lane];
        #pragma unroll
        for (int o = 16; o > 0; o >>= 1) s += __shfl_down_sync(0xffffffff, s, o);
        if (lane == 0) g_bsum[blockIdx.x] = s;
    }
}

__global__ void bsum_scan_kernel(int nblk) {
    int run = 0;
    for (int i = 0; i < nblk; i++) { g_boff[i] = run; run += g_bsum[i]; }
    g_off[NN] = run;
}

__global__ void off_write_kernel() {
    __shared__ int s[1024];
    int t = threadIdx.x;
    int i = blockIdx.x * 1024 + t;
    int v = (i < NN) ? g_deg[i] : 0;
    s[t] = v;
    __syncthreads();
    #pragma unroll
    for (int o = 1; o < 1024; o <<= 1) {
        int u = (t >= o) ? s[t - o] : 0;
        __syncthreads();
        s[t] += u;
        __syncthreads();
    }
    if (i < NN) g_off[i] = g_boff[blockIdx.x] + s[t] - v;
}

__global__ void csr_fill_kernel(const int* __restrict__ src, const int* __restrict__ dst,
                                const float* __restrict__ ea) {
    int e = blockIdx.x * blockDim.x + threadIdx.x;
    if (e >= EE) return;
    int d = dst[e];
    int pos = g_off[d] + atomicAdd(&g_fill[d], 1);
    g_srccsr[pos] = src[e];
    g_eacsr[pos] = make_float4(ea[e * 3 + 0], ea[e * 3 + 1], ea[e * 3 + 2], 0.f);
}

// ---------------- A conversion: fp32 -> bf16 hi/lo, m16n8k16 fragment order --
__global__ void convertA_kernel(const float* __restrict__ src, int K, int KQ) {
    int id = blockIdx.x * 256 + threadIdx.x;
    int total = MT * KQ * 256;
    if (id >= total) return;
    int lane = id & 31;
    int t = id >> 5;
    int m16 = t & 7; t >>= 3;
    int kq = t % KQ;
    int mt = t / KQ;
    int g = lane >> 2, tig = lane & 3;
    int row0 = mt * 128 + m16 * 16 + g, row1 = row0 + 8;
    int k0 = kq * 16 + tig * 2, k1 = k0 + 8;

    float a00 = (row0 < NN) ? src[(size_t)row0 * K + k0]     : 0.f;
    float a01 = (row0 < NN) ? src[(size_t)row0 * K + k0 + 1] : 0.f;
    float a10 = (row1 < NN) ? src[(size_t)row1 * K + k0]     : 0.f;
    float a11 = (row1 < NN) ? src[(size_t)row1 * K + k0 + 1] : 0.f;
    float a02 = (row0 < NN) ? src[(size_t)row0 * K + k1]     : 0.f;
    float a03 = (row0 < NN) ? src[(size_t)row0 * K + k1 + 1] : 0.f;
    float a12 = (row1 < NN) ? src[(size_t)row1 * K + k1]     : 0.f;
    float a13 = (row1 < NN) ? src[(size_t)row1 * K + k1 + 1] : 0.f;

    float h00 = tobf(a00), h01 = tobf(a01), h10 = tobf(a10), h11 = tobf(a11);
    float h02 = tobf(a02), h03 = tobf(a03), h12 = tobf(a12), h13 = tobf(a13);
    uint4 hi, lo;
    hi.x = packbf(h00, h01); lo.x = packbf(a00 - h00, a01 - h01);
    hi.y = packbf(h10, h11); lo.y = packbf(a10 - h10, a11 - h11);
    hi.z = packbf(h02, h03); lo.z = packbf(a02 - h02, a03 - h03);
    hi.w = packbf(h12, h13); lo.w = packbf(a12 - h12, a13 - h13);
    *(uint4*)(g_aph + (size_t)id * 4) = hi;
    *(uint4*)(g_apl + (size_t)id * 4) = lo;
}

// ---------------- W conversion ----------------------------------------------
__global__ void convertW_kernel(const float* __restrict__ Wl0, const float* __restrict__ Wr0,
                                const float* __restrict__ Wl1, const float* __restrict__ Wr1) {
    int id = blockIdx.x * 256 + threadIdx.x;   // total 65536
    int widx = id >> 14;
    int rem = id & 16383;
    int kq = rem >> 10;
    int n8 = (rem >> 5) & 31;
    int lane = rem & 31;
    int KQw = (widx < 2) ? 16 : 4;
    if (kq >= KQw) return;
    const float* W = (widx == 0) ? Wl0 : (widx == 1) ? Wr0 : (widx == 2) ? Wl1 : Wr1;
    int g = lane >> 2, tig = lane & 3;
    int n = n8 * 8 + g;
    int kb = kq * 16;
    float v0 = W[(size_t)(kb + 2 * tig) * 256 + n];
    float v1 = W[(size_t)(kb + 2 * tig + 1) * 256 + n];
    float v2 = W[(size_t)(kb + 2 * tig + 8) * 256 + n];
    float v3 = W[(size_t)(kb + 2 * tig + 9) * 256 + n];
    float h0 = tobf(v0), h1 = tobf(v1), h2 = tobf(v2), h3 = tobf(v3);
    int off = widx * 32768 + kq * 2048 + n8 * 64 + lane * 2;
    g_wph[off] = packbf(h0, h1); g_wph[off + 1] = packbf(h2, h3);
    g_wpl[off] = packbf(v0 - h0, v1 - h1); g_wpl[off + 1] = packbf(v2 - h2, v3 - h3);
}

// ---------------- fused bf16 3-term tensor GEMM ------------------------------
__global__ __launch_bounds__(256, 2)
void gemm_fused_kernel(const uint32_t* __restrict__ aph, const uint32_t* __restrict__ apl,
                       const uint32_t* __restrict__ wLh, const uint32_t* __restrict__ wLl,
                       const uint32_t* __restrict__ wRh, const uint32_t* __restrict__ wRl,
                       const float* __restrict__ biasL, const float* __restrict__ biasR,
                       float* __restrict__ CL, float* __restrict__ CR, int KQ) {
    extern __shared__ uint32_t sm[];
    uint32_t sb = smem_u32(sm);
    const int tid = threadIdx.x, lane = tid & 31, wid = tid >> 5;
    const int wm = wid >> 1, wn = wid & 1;
    const int mt = blockIdx.x;
    const int ysel = blockIdx.y;
    const uint32_t* bph = (ysel < 2) ? wLh : wRh;
    const uint32_t* bpl = (ysel < 2) ? wLl : wRl;
    const float* bias   = (ysel < 2) ? biasL : biasR;
    float* C            = (ysel < 2) ? CL : CR;
    const int bn8 = (ysel & 1) * 16;
    const int nch = KQ >> 1;

    const uint32_t* agh = aph + (size_t)mt * KQ * 1024;
    const uint32_t* agl = apl + (size_t)mt * KQ * 1024;

    float acc[2][8][4];
    #pragma unroll
    for (int mi = 0; mi < 2; mi++)
        #pragma unroll
        for (int ni = 0; ni < 8; ni++)
            #pragma unroll
            for (int r = 0; r < 4; r++) acc[mi][ni][r] = 0.f;

    auto load_chunk = [&](int ch, int s) {
        uint32_t base = sb + s * 32768;
        #pragma unroll
        for (int i = 0; i < 2; i++) {
            int kq = ch * 2 + i;
            CP_ASYNC16(base + (i * 1024 + tid * 4) * 4,          agh + kq * 1024 + tid * 4);
            CP_ASYNC16(base + (2048 + i * 1024 + tid * 4) * 4,   agl + kq * 1024 + tid * 4);
            CP_ASYNC16(base + (4096 + i * 1024 + tid * 4) * 4,   bph + kq * 2048 + bn8 * 64 + tid * 4);
            CP_ASYNC16(base + (6144 + i * 1024 + tid * 4) * 4,   bpl + kq * 2048 + bn8 * 64 + tid * 4);
        }
        CP_COMMIT;
    };

    load_chunk(0, 0);
    if (nch > 1) load_chunk(1, 1);

    for (int ch = 0; ch < nch; ch++) {
        if (ch + 1 < nch) { CP_WAIT(1); } else { CP_WAIT(0); }
        __syncthreads();
        if (ch + 2 < nch) load_chunk(ch + 2, (ch + 2) % 3);

        const uint32_t* st = sm + (ch % 3) * 8192;
        #pragma unroll
        for (int i = 0; i < 2; i++) {
            uint32_t ah[2][4], al[2][4];
            #pragma unroll
            for (int mi = 0; mi < 2; mi++) {
                int m16 = wm * 2 + mi;
                uint4 vh = *(const uint4*)(st + i * 1024 + m16 * 128 + lane * 4);
                uint4 vl = *(const uint4*)(st + 2048 + i * 1024 + m16 * 128 + lane * 4);
                ah[mi][0] = vh.x; ah[mi][1] = vh.y; ah[mi][2] = vh.z; ah[mi][3] = vh.w;
                al[mi][0] = vl.x; al[mi][1] = vl.y; al[mi][2] = vl.z; al[mi][3] = vl.w;
            }
            #pragma unroll
            for (int ni = 0; ni < 8; ni++) {
                int n8l = wn * 8 + ni;
                uint2 bhv = *(const uint2*)(st + 4096 + i * 1024 + n8l * 64 + lane * 2);
                uint2 blv = *(const uint2*)(st + 6144 + i * 1024 + n8l * 64 + lane * 2);
                uint32_t bh[2] = {bhv.x, bhv.y}, bl[2] = {blv.x, blv.y};
                #pragma unroll
                for (int mi = 0; mi < 2; mi++) {
                    mma_bf16(acc[mi][ni], al[mi], bh);
                    mma_bf16(acc[mi][ni], ah[mi], bl);
                    mma_bf16(acc[mi][ni], ah[mi], bh);
                }
            }
        }
        __syncthreads();
    }

    const int g = lane >> 2, tig = lane & 3;
    #pragma unroll
    for (int mi = 0; mi < 2; mi++) {
        int row = mt * 128 + wm * 32 + mi * 16 + g;
        #pragma unroll
        for (int ni = 0; ni < 8; ni++) {
            int col = (ysel & 1) * 128 + wn * 64 + ni * 8 + tig * 2;
            float b0 = __ldg(bias + col), b1 = __ldg(bias + col + 1);
            if (row < NN)
                *(float2*)(C + (size_t)row * 256 + col) =
                    make_float2(acc[mi][ni][0] + b0, acc[mi][ni][1] + b1);
            if (row + 8 < NN)
                *(float2*)(C + (size_t)(row + 8) * 256 + col) =
                    make_float2(acc[mi][ni][2] + b0, acc[mi][ni][3] + b1);
        }
    }
}

// ---------------- GATv2 aggregation: warp/node, 4 edges per iteration --------
__global__ __launch_bounds__(256)
void gat_agg_kernel(const float* __restrict__ xl, const float* __restrict__ xr,
                    const float* __restrict__ We, const float* __restrict__ att,
                    const float* __restrict__ bias, float* __restrict__ out) {
    int warp = (blockIdx.x * blockDim.x + threadIdx.x) >> 5;
    if (warp >= NN) return;
    int lane  = threadIdx.x & 31;
    int node  = warp;
    int jbase = lane * 8;

    float we0[8], we1[8], we2[8], attv[8], xrv[8];
    #pragma unroll
    for (int i = 0; i < 8; i++) {
        int j = jbase + i;
        we0[i]  = We[j];
        we1[i]  = We[256 + j];
        we2[i]  = We[512 + j];
        attv[i] = att[j];
        xrv[i]  = xr[(size_t)node * HC + j];
    }

    float mx = -1e30f, den = 0.f;
    float acc[8] = {};
    float sea0 = 0.f, sea1 = 0.f, sea2 = 0.f;
    int e0 = g_off[node], e1 = g_off[node + 1];

    auto update1 = [&](const float* xlv, float ea0, float ea1, float ea2) {
        float part = 0.f;
        #pragma unroll
        for (int i = 0; i < 8; i++) {
            float m = xlv[i] + xrv[i] + ea0 * we0[i] + ea1 * we1[i] + ea2 * we2[i];
            m = (m > 0.f) ? m : 0.2f * m;
            part += m * attv[i];
        }
        part += __shfl_xor_sync(0xffffffff, part, 1);
        part += __shfl_xor_sync(0xffffffff, part, 2);
        part += __shfl_xor_sync(0xffffffff, part, 4);
        float nm = fmaxf(mx, part);
        float sc = __expf(mx - nm);
        float pw = __expf(part - nm);
        den = den * sc + pw;
        #pragma unroll
        for (int i = 0; i < 8; i++) acc[i] = acc[i] * sc + pw * xlv[i];
        mx = nm;
    };

    int t = e0;
    // 4-edge batched iterations: 8 gathers in flight, independent shfls/exps,
    // single combined online-softmax update.
    for (; t + 4 <= e1; t += 4) {
        int s[4];
        #pragma unroll
        for (int j = 0; j < 4; j++) s[j] = g_srccsr[t + j];

        float xv[4][8];
        #pragma unroll
        for (int j = 0; j < 4; j++) {
            const float4* p = (const float4*)(xl + (size_t)s[j] * HC + jbase);
            float4 a = __ldg(p), b = __ldg(p + 1);
            xv[j][0] = a.x; xv[j][1] = a.y; xv[j][2] = a.z; xv[j][3] = a.w;
            xv[j][4] = b.x; xv[j][5] = b.y; xv[j][6] = b.z; xv[j][7] = b.w;
        }

        float part[4];
        #pragma unroll
        for (int j = 0; j < 4; j++) {
            float4 A = __ldg(&g_eacsr[t + j]);
            sea0 += A.x; sea1 += A.y; sea2 += A.z;
            float p = 0.f;
            #pragma unroll
            for (int i = 0; i < 8; i++) {
                float m = xv[j][i] + xrv[i] + A.x * we0[i] + A.y * we1[i] + A.z * we2[i];
                m = (m > 0.f) ? m : 0.2f * m;
                p += m * attv[i];
            }
            part[j] = p;
        }
        #pragma unroll
        for (int o = 1; o <= 4; o <<= 1) {
            #pragma unroll
            for (int j = 0; j < 4; j++)
                part[j] += __shfl_xor_sync(0xffffffff, part[j], o);
        }

        float nm = fmaxf(fmaxf(part[0], part[1]), fmaxf(part[2], part[3]));
        nm = fmaxf(nm, mx);
        float sc = __expf(mx - nm);
        float w0 = __expf(part[0] - nm), w1 = __expf(part[1] - nm);
        float w2 = __expf(part[2] - nm), w3 = __expf(part[3] - nm);
        den = den * sc + ((w0 + w1) + (w2 + w3));
        #pragma unroll
        for (int i = 0; i < 8; i++) {
            float a = acc[i] * sc;
            a += w0 * xv[0][i];
            a += w1 * xv[1][i];
            a += w2 * xv[2][i];
            a += w3 * xv[3][i];
            acc[i] = a;
        }
        mx = nm;
    }

    // tail edges (<4)
    for (; t < e1; t++) {
        int sA = g_srccsr[t];
        float4 A = __ldg(&g_eacsr[t]);
        sea0 += A.x; sea1 += A.y; sea2 += A.z;
        const float4* p = (const float4*)(xl + (size_t)sA * HC + jbase);
        float4 a = __ldg(p), b = __ldg(p + 1);
        float xlv[8] = {a.x, a.y, a.z, a.w, b.x, b.y, b.z, b.w};
        update1(xlv, A.x, A.y, A.z);
    }

    // self loop (edge_attr = mean of incoming)
    {
        float inv = 1.f / fmaxf((float)(e1 - e0), 1.f);
        const float4* p = (const float4*)(xl + (size_t)node * HC + jbase);
        float4 a = __ldg(p), b = __ldg(p + 1);
        float xlv[8] = {a.x, a.y, a.z, a.w, b.x, b.y, b.z, b.w};
        update1(xlv, sea0 * inv, sea1 * inv, sea2 * inv);
    }

    float inv = 1.f / den;
    #pragma unroll
    for (int i = 0; i < 8; i++) {
        float r = acc[i] * inv;
        r += __shfl_xor_sync(0xffffffff, r, 8);
        r += __shfl_xor_sync(0xffffffff, r, 16);
        acc[i] = r * 0.25f;
    }
    if (lane < 8) {
        #pragma unroll
        for (int i = 0; i < 8; i++) {
            int c = jbase + i;
            out[(size_t)node * CC + c] = fmaxf(acc[i] + bias[c], 0.f);
        }
    }
}

// ---------------- final projection ------------------------------------------
__global__ __launch_bounds__(256)
void mu_kernel(const float* __restrict__ h, const float* __restrict__ Wmu,
               const float* __restrict__ bmu, float* __restrict__ out) {
    __shared__ float sW[CC * LAT];
    __shared__ float sb[LAT];
    int tid = threadIdx.x;
    for (int i = tid; i < CC * LAT; i += 256) sW[i] = Wmu[i];
    if (tid < LAT) sb[tid] = bmu[tid];
    __syncthreads();
    int warp = tid >> 5, lane = tid & 31;
    int node = blockIdx.x * 8 + warp;
    if (node >= NN) return;
    const float* hr = h + (size_t)node * CC;
    float sum = sb[lane];
    #pragma unroll
    for (int c = 0; c < CC; c++)
        sum += hr[c] * sW[c * LAT + lane];
    out[(size_t)node * LAT + lane] = sum;
}

// ---------------- host launcher ---------------------------------------------
extern "C" void kernel_launch(void* const* d_in, const int* in_sizes, int n_in,
                              void* d_out, int out_size) {
    const float* x   = (const float*)d_in[0];
    const int*   ei  = (const int*)  d_in[1];
    const float* ea  = (const float*)d_in[2];
    const float* Wl0 = (const float*)d_in[3];
    const float* bl0 = (const float*)d_in[4];
    const float* Wr0 = (const float*)d_in[5];
    const float* br0 = (const float*)d_in[6];
    const float* We0 = (const float*)d_in[7];
    const float* at0 = (const float*)d_in[8];
    const float* bi0 = (const float*)d_in[9];
    const float* Wl1 = (const float*)d_in[10];
    const float* bl1 = (const float*)d_in[11];
    const float* Wr1 = (const float*)d_in[12];
    const float* br1 = (const float*)d_in[13];
    const float* We1 = (const float*)d_in[14];
    const float* at1 = (const float*)d_in[15];
    const float* bi1 = (const float*)d_in[16];
    const float* Wmu = (const float*)d_in[17];
    const float* bmu = (const float*)d_in[18];
    float* out = (float*)d_out;

    const int* src = ei;
    const int* dst = ei + EE;

    float* xl; cudaGetSymbolAddress((void**)&xl, g_xl);
    float* xr; cudaGetSymbolAddress((void**)&xr, g_xr);
    float* h ; cudaGetSymbolAddress((void**)&h , g_h );
    uint32_t* aph; cudaGetSymbolAddress((void**)&aph, g_aph);
    uint32_t* apl; cudaGetSymbolAddress((void**)&apl, g_apl);
    uint32_t* wph; cudaGetSymbolAddress((void**)&wph, g_wph);
    uint32_t* wpl; cudaGetSymbolAddress((void**)&wpl, g_wpl);

    cudaFuncSetAttribute(gemm_fused_kernel, cudaFuncAttributeMaxDynamicSharedMemorySize, 98304);

    const int SCAN_BLOCKS = (NN + 1023) / 1024;
    dim3 gemm_grid(MT, 4);
    dim3 agg_grid((NN + 7) / 8);

    init_kernel<<<(NN + 255) / 256, 256>>>();
    convertA_kernel<<<(MT * 16 * 256 + 255) / 256, 256>>>(x, 256, 16);
    convertW_kernel<<<65536 / 256, 256>>>(Wl0, Wr0, Wl1, Wr1);

    gemm_fused_kernel<<<gemm_grid, 256, 98304>>>(aph, apl,
        wph + 0 * 32768, wpl + 0 * 32768, wph + 1 * 32768, wpl + 1 * 32768,
        bl0, br0, xl, xr, 16);

    edge_deg_kernel<<<(EE + 255) / 256, 256>>>(dst);
    deg_blocksum_kernel<<<SCAN_BLOCKS, 1024>>>();
    bsum_scan_kernel<<<1, 1>>>(SCAN_BLOCKS);
    off_write_kernel<<<SCAN_BLOCKS, 1024>>>();
    csr_fill_kernel<<<(EE + 255) / 256, 256>>>(src, dst, ea);

    gat_agg_kernel<<<agg_grid, 256>>>(xl, xr, We0, at0, bi0, h);

    convertA_kernel<<<(MT * 4 * 256 + 255) / 256, 256>>>(h, 64, 4);
    gemm_fused_kernel<<<gemm_grid, 256, 98304>>>(aph, apl,
        wph + 2 * 32768, wpl + 2 * 32768, wph + 3 * 32768, wpl + 3 * 32768,
        bl1, br1, xl, xr, 4);

    gat_agg_kernel<<<agg_grid, 256>>>(xl, xr, We1, at1, bi1, h);

    mu_kernel<<<(NN + 7) / 8, 256>>>(h, Wmu, bmu, out);
}

// round 10
// speedup vs baseline: 1.5561x; 1.0075x over previous
#include <cuda_runtime.h>
#include <cuda_bf16.h>
#include <stdint.h>
#include <cstdint>
#include <math.h>

// Problem constants
#define NN   50000
#define EE   800000
#define IN_D 256
#define HC   256
#define HH   4
#define CC   64
#define LAT  32
#define MT   391          // ceil(50000/128)

// ---------------- device scratch ------------------------------------------
__device__ float g_xl[NN * HC];
__device__ float g_xr[NN * HC];
__device__ float g_h [NN * CC];
__device__ uint32_t g_aph[MT * 16 * 1024];   // A hi plane, bf16x2 fragment-permuted
__device__ uint32_t g_apl[MT * 16 * 1024];   // A lo plane
__device__ uint32_t g_wph[4 * 32768];        // W hi planes, fragment-permuted (paired n8)
__device__ uint32_t g_wpl[4 * 32768];
__device__ int    g_deg [NN];
__device__ int    g_off [NN + 1];
__device__ int    g_fill[NN];
__device__ int    g_srccsr[EE];              // src node per CSR slot
__device__ float4 g_eacsr[EE];               // edge_attr per CSR slot (xyz used)
__device__ int    g_bsum[64];
__device__ int    g_boff[64];

// ---------------- helpers ---------------------------------------------------
__device__ __forceinline__ uint32_t smem_u32(const void* p) {
    uint32_t a;
    asm("{ .reg .u64 t; cvta.to.shared.u64 t, %1; cvt.u32.u64 %0, t; }" : "=r"(a) : "l"(p));
    return a;
}
__device__ __forceinline__ float tobf(float v) {
    return __bfloat162float(__float2bfloat16(v));
}
__device__ __forceinline__ uint32_t packbf(float a, float b) {
    __nv_bfloat162 v = __floats2bfloat162_rn(a, b);
    return *reinterpret_cast<uint32_t*>(&v);
}
__device__ __forceinline__ void mma_bf16(float* c, const uint32_t* a, const uint32_t* b) {
    asm volatile(
        "mma.sync.aligned.m16n8k16.row.col.f32.bf16.bf16.f32 "
        "{%0,%1,%2,%3}, {%4,%5,%6,%7}, {%8,%9}, {%0,%1,%2,%3};"
        : "+f"(c[0]), "+f"(c[1]), "+f"(c[2]), "+f"(c[3])
        : "r"(a[0]), "r"(a[1]), "r"(a[2]), "r"(a[3]), "r"(b[0]), "r"(b[1]));
}
#define CP_ASYNC16(dst, src) \
    asm volatile("cp.async.ca.shared.global [%0], [%1], 16;" :: "r"((uint32_t)(dst)), "l"(src))
#define CP_COMMIT  asm volatile("cp.async.commit_group;" ::: "memory")
#define CP_WAIT(n) asm volatile("cp.async.wait_group %0;" :: "n"(n) : "memory")

// ---------------- graph preprocessing ---------------------------------------
__global__ void init_kernel() {
    int i = blockIdx.x * blockDim.x + threadIdx.x;
    if (i < NN) { g_deg[i] = 0; g_fill[i] = 0; }
}

__global__ void edge_deg_kernel(const int* __restrict__ dst) {
    int e = blockIdx.x * blockDim.x + threadIdx.x;
    if (e >= EE) return;
    atomicAdd(&g_deg[dst[e]], 1);
}

__global__ void deg_blocksum_kernel() {
    int i = blockIdx.x * 1024 + threadIdx.x;
    int v = (i < NN) ? g_deg[i] : 0;
    __shared__ int ws[32];
    int lane = threadIdx.x & 31, wid = threadIdx.x >> 5;
    #pragma unroll
    for (int o = 16; o > 0; o >>= 1) v += __shfl_down_sync(0xffffffff, v, o);
    if (lane == 0) ws[wid] = v;
    __syncthreads();
    if (wid == 0) {
        int s = ws[lane];
        #pragma unroll
        for (int o = 16; o > 0; o >>= 1) s += __shfl_down_sync(0xffffffff, s, o);
        if (lane == 0) g_bsum[blockIdx.x] = s;
    }
}

__global__ void bsum_scan_kernel(int nblk) {
    int run = 0;
    for (int i = 0; i < nblk; i++) { g_boff[i] = run; run += g_bsum[i]; }
    g_off[NN] = run;
}

__global__ void off_write_kernel() {
    __shared__ int s[1024];
    int t = threadIdx.x;
    int i = blockIdx.x * 1024 + t;
    int v = (i < NN) ? g_deg[i] : 0;
    s[t] = v;
    __syncthreads();
    #pragma unroll
    for (int o = 1; o < 1024; o <<= 1) {
        int u = (t >= o) ? s[t - o] : 0;
        __syncthreads();
        s[t] += u;
        __syncthreads();
    }
    if (i < NN) g_off[i] = g_boff[blockIdx.x] + s[t] - v;
}

__global__ void csr_fill_kernel(const int* __restrict__ src, const int* __restrict__ dst,
                                const float* __restrict__ ea) {
    int e = blockIdx.x * blockDim.x + threadIdx.x;
    if (e >= EE) return;
    int d = dst[e];
    int pos = g_off[d] + atomicAdd(&g_fill[d], 1);
    g_srccsr[pos] = src[e];
    g_eacsr[pos] = make_float4(ea[e * 3 + 0], ea[e * 3 + 1], ea[e * 3 + 2], 0.f);
}

// ---------------- A conversion: fp32 -> bf16 hi/lo, m16n8k16 fragment order --
__global__ void convertA_kernel(const float* __restrict__ src, int K, int KQ) {
    int id = blockIdx.x * 256 + threadIdx.x;
    int total = MT * KQ * 256;
    if (id >= total) return;
    int lane = id & 31;
    int t = id >> 5;
    int m16 = t & 7; t >>= 3;
    int kq = t % KQ;
    int mt = t / KQ;
    int g = lane >> 2, tig = lane & 3;
    int row0 = mt * 128 + m16 * 16 + g, row1 = row0 + 8;
    int k0 = kq * 16 + tig * 2, k1 = k0 + 8;

    float a00 = (row0 < NN) ? src[(size_t)row0 * K + k0]     : 0.f;
    float a01 = (row0 < NN) ? src[(size_t)row0 * K + k0 + 1] : 0.f;
    float a10 = (row1 < NN) ? src[(size_t)row1 * K + k0]     : 0.f;
    float a11 = (row1 < NN) ? src[(size_t)row1 * K + k0 + 1] : 0.f;
    float a02 = (row0 < NN) ? src[(size_t)row0 * K + k1]     : 0.f;
    float a03 = (row0 < NN) ? src[(size_t)row0 * K + k1 + 1] : 0.f;
    float a12 = (row1 < NN) ? src[(size_t)row1 * K + k1]     : 0.f;
    float a13 = (row1 < NN) ? src[(size_t)row1 * K + k1 + 1] : 0.f;

    float h00 = tobf(a00), h01 = tobf(a01), h10 = tobf(a10), h11 = tobf(a11);
    float h02 = tobf(a02), h03 = tobf(a03), h12 = tobf(a12), h13 = tobf(a13);
    uint4 hi, lo;
    hi.x = packbf(h00, h01); lo.x = packbf(a00 - h00, a01 - h01);
    hi.y = packbf(h10, h11); lo.y = packbf(a10 - h10, a11 - h11);
    hi.z = packbf(h02, h03); lo.z = packbf(a02 - h02, a03 - h03);
    hi.w = packbf(h12, h13); lo.w = packbf(a12 - h12, a13 - h13);
    *(uint4*)(g_aph + (size_t)id * 4) = hi;
    *(uint4*)(g_apl + (size_t)id * 4) = lo;
}

// ---------------- W conversion: paired-n8 B-fragment order -------------------
// layout per widx: [kq16][pair:16][lane:32][4 u32] where pair packs n8 {2p,2p+1}
__global__ void convertW_kernel(const float* __restrict__ Wl0, const float* __restrict__ Wr0,
                                const float* __restrict__ Wl1, const float* __restrict__ Wr1) {
    int id = blockIdx.x * 256 + threadIdx.x;   // total 65536
    int widx = id >> 14;
    int rem = id & 16383;
    int kq = rem >> 10;
    int n8 = (rem >> 5) & 31;
    int lane = rem & 31;
    int KQw = (widx < 2) ? 16 : 4;
    if (kq >= KQw) return;
    const float* W = (widx == 0) ? Wl0 : (widx == 1) ? Wr0 : (widx == 2) ? Wl1 : Wr1;
    int g = lane >> 2, tig = lane & 3;
    int n = n8 * 8 + g;
    int kb = kq * 16;
    float v0 = W[(size_t)(kb + 2 * tig) * 256 + n];
    float v1 = W[(size_t)(kb + 2 * tig + 1) * 256 + n];
    float v2 = W[(size_t)(kb + 2 * tig + 8) * 256 + n];
    float v3 = W[(size_t)(kb + 2 * tig + 9) * 256 + n];
    float h0 = tobf(v0), h1 = tobf(v1), h2 = tobf(v2), h3 = tobf(v3);
    int off = widx * 32768 + kq * 2048 + (n8 >> 1) * 128 + lane * 4 + (n8 & 1) * 2;
    g_wph[off] = packbf(h0, h1); g_wph[off + 1] = packbf(h2, h3);
    g_wpl[off] = packbf(v0 - h0, v1 - h1); g_wpl[off + 1] = packbf(v2 - h2, v3 - h3);
}

// ---------------- fused bf16 3-term tensor GEMM ------------------------------
__global__ __launch_bounds__(256, 2)
void gemm_fused_kernel(const uint32_t* __restrict__ aph, const uint32_t* __restrict__ apl,
                       const uint32_t* __restrict__ wLh, const uint32_t* __restrict__ wLl,
                       const uint32_t* __restrict__ wRh, const uint32_t* __restrict__ wRl,
                       const float* __restrict__ biasL, const float* __restrict__ biasR,
                       float* __restrict__ CL, float* __restrict__ CR, int KQ) {
    extern __shared__ uint32_t sm[];
    uint32_t sb = smem_u32(sm);
    const int tid = threadIdx.x, lane = tid & 31, wid = tid >> 5;
    const int wm = wid >> 1, wn = wid & 1;
    const int mt = blockIdx.x;
    const int ysel = blockIdx.y;
    const uint32_t* bph = (ysel < 2) ? wLh : wRh;
    const uint32_t* bpl = (ysel < 2) ? wLl : wRl;
    const float* bias   = (ysel < 2) ? biasL : biasR;
    float* C            = (ysel < 2) ? CL : CR;
    const int bn8 = (ysel & 1) * 16;
    const int nch = KQ >> 1;

    const uint32_t* agh = aph + (size_t)mt * KQ * 1024;
    const uint32_t* agl = apl + (size_t)mt * KQ * 1024;

    float acc[2][8][4];
    #pragma unroll
    for (int mi = 0; mi < 2; mi++)
        #pragma unroll
        for (int ni = 0; ni < 8; ni++)
            #pragma unroll
            for (int r = 0; r < 4; r++) acc[mi][ni][r] = 0.f;

    auto load_chunk = [&](int ch, int s) {
        uint32_t base = sb + s * 32768;
        #pragma unroll
        for (int i = 0; i < 2; i++) {
            int kq = ch * 2 + i;
            CP_ASYNC16(base + (i * 1024 + tid * 4) * 4,          agh + kq * 1024 + tid * 4);
            CP_ASYNC16(base + (2048 + i * 1024 + tid * 4) * 4,   agl + kq * 1024 + tid * 4);
            CP_ASYNC16(base + (4096 + i * 1024 + tid * 4) * 4,   bph + kq * 2048 + bn8 * 64 + tid * 4);
            CP_ASYNC16(base + (6144 + i * 1024 + tid * 4) * 4,   bpl + kq * 2048 + bn8 * 64 + tid * 4);
        }
        CP_COMMIT;
    };

    load_chunk(0, 0);
    if (nch > 1) load_chunk(1, 1);

    for (int ch = 0; ch < nch; ch++) {
        if (ch + 1 < nch) { CP_WAIT(1); } else { CP_WAIT(0); }
        __syncthreads();
        if (ch + 2 < nch) load_chunk(ch + 2, (ch + 2) % 3);

        const uint32_t* st = sm + (ch % 3) * 8192;
        #pragma unroll
        for (int i = 0; i < 2; i++) {
            uint32_t ah[2][4], al[2][4];
            #pragma unroll
            for (int mi = 0; mi < 2; mi++) {
                int m16 = wm * 2 + mi;
                uint4 vh = *(const uint4*)(st + i * 1024 + m16 * 128 + lane * 4);
                uint4 vl = *(const uint4*)(st + 2048 + i * 1024 + m16 * 128 + lane * 4);
                ah[mi][0] = vh.x; ah[mi][1] = vh.y; ah[mi][2] = vh.z; ah[mi][3] = vh.w;
                al[mi][0] = vl.x; al[mi][1] = vl.y; al[mi][2] = vl.z; al[mi][3] = vl.w;
            }
            #pragma unroll
            for (int pp = 0; pp < 4; pp++) {
                uint4 bhv = *(const uint4*)(st + 4096 + i * 1024 + (wn * 4 + pp) * 128 + lane * 4);
                uint4 blv = *(const uint4*)(st + 6144 + i * 1024 + (wn * 4 + pp) * 128 + lane * 4);
                uint32_t bh0[2] = {bhv.x, bhv.y}, bl0[2] = {blv.x, blv.y};
                uint32_t bh1[2] = {bhv.z, bhv.w}, bl1[2] = {blv.z, blv.w};
                #pragma unroll
                for (int mi = 0; mi < 2; mi++) {
                    mma_bf16(acc[mi][pp * 2],     al[mi], bh0);
                    mma_bf16(acc[mi][pp * 2],     ah[mi], bl0);
                    mma_bf16(acc[mi][pp * 2],     ah[mi], bh0);
                    mma_bf16(acc[mi][pp * 2 + 1], al[mi], bh1);
                    mma_bf16(acc[mi][pp * 2 + 1], ah[mi], bl1);
                    mma_bf16(acc[mi][pp * 2 + 1], ah[mi], bh1);
                }
            }
        }
        __syncthreads();
    }

    const int g = lane >> 2, tig = lane & 3;
    #pragma unroll
    for (int mi = 0; mi < 2; mi++) {
        int row = mt * 128 + wm * 32 + mi * 16 + g;
        #pragma unroll
        for (int ni = 0; ni < 8; ni++) {
            int col = (ysel & 1) * 128 + wn * 64 + ni * 8 + tig * 2;
            float b0 = __ldg(bias + col), b1 = __ldg(bias + col + 1);
            if (row < NN)
                *(float2*)(C + (size_t)row * 256 + col) =
                    make_float2(acc[mi][ni][0] + b0, acc[mi][ni][1] + b1);
            if (row + 8 < NN)
                *(float2*)(C + (size_t)(row + 8) * 256 + col) =
                    make_float2(acc[mi][ni][2] + b0, acc[mi][ni][3] + b1);
        }
    }
}

// ---------------- GATv2 aggregation: warp/node, cp.async pipelined gathers ---
// 128 threads = 4 warps/block; each warp owns 8KB smem (2 stages x 4 edges x 1KB).
__global__ __launch_bounds__(128)
void gat_agg_kernel(const float* __restrict__ xl, const float* __restrict__ xr,
                    const float* __restrict__ We, const float* __restrict__ att,
                    const float* __restrict__ bias, float* __restrict__ out) {
    __shared__ uint4 sg[4 * 512];      // 32 KB, 16B-aligned (cp.async requirement)
    int wib  = threadIdx.x >> 5;
    int node = blockIdx.x * 4 + wib;
    if (node >= NN) return;
    int lane  = threadIdx.x & 31;
    int jbase = lane * 8;

    uint32_t wbase = smem_u32(sg) + wib * 8192;
    uint32_t loff  = (uint32_t)(lane * 32);
    uint32_t swz   = loff ^ ((loff >> 3) & 0x70);   // SW128 swizzle of lane slice
    // second 16B chunk of the slice: swizzle(loff+16) == swz ^ 16 (bits 7-9 unchanged)

    float we0[8], we1[8], we2[8], attv[8], xrv[8];
    #pragma unroll
    for (int i = 0; i < 8; i++) {
        int j = jbase + i;
        we0[i]  = We[j];
        we1[i]  = We[256 + j];
        we2[i]  = We[512 + j];
        attv[i] = att[j];
        xrv[i]  = xr[(size_t)node * HC + j];
    }

    float mx = -1e30f, den = 0.f;
    float acc[8] = {};
    float sea0 = 0.f, sea1 = 0.f, sea2 = 0.f;
    int e0 = g_off[node], e1 = g_off[node + 1];
    int deg = e1 - e0;
    int nb = deg >> 2;

    auto issue = [&](int b, const int* s4) {
        uint32_t dst = wbase + (b & 1) * 4096;
        #pragma unroll
        for (int j = 0; j < 4; j++) {
            const float* src = xl + (size_t)s4[j] * HC + jbase;
            CP_ASYNC16(dst + j * 1024 + swz, src);
            CP_ASYNC16(dst + j * 1024 + (swz ^ 16), src + 4);
        }
        CP_COMMIT;
    };

    auto update1 = [&](const float* xlv, float ea0, float ea1, float ea2) {
        float part = 0.f;
        #pragma unroll
        for (int i = 0; i < 8; i++) {
            float m = xlv[i] + xrv[i] + ea0 * we0[i] + ea1 * we1[i] + ea2 * we2[i];
            m = (m > 0.f) ? m : 0.2f * m;
            part += m * attv[i];
        }
        part += __shfl_xor_sync(0xffffffff, part, 1);
        part += __shfl_xor_sync(0xffffffff, part, 2);
        part += __shfl_xor_sync(0xffffffff, part, 4);
        float nm = fmaxf(mx, part);
        float sc = __expf(mx - nm);
        float pw = __expf(part - nm);
        den = den * sc + pw;
        #pragma unroll
        for (int i = 0; i < 8; i++) acc[i] = acc[i] * sc + pw * xlv[i];
        mx = nm;
    };

    // pipeline prologue
    if (nb > 0) {
        int s4[4];
        #pragma unroll
        for (int j = 0; j < 4; j++) s4[j] = g_srccsr[e0 + j];
        issue(0, s4);
    }
    if (nb > 1) {
        int s4[4];
        #pragma unroll
        for (int j = 0; j < 4; j++) s4[j] = g_srccsr[e0 + 4 + j];
        issue(1, s4);
    }

    for (int n = 0; n < nb; n++) {
        int t = e0 + n * 4;
        int sN[4];
        bool hasN2 = (n + 2 < nb);
        if (hasN2) {
            #pragma unroll
            for (int j = 0; j < 4; j++) sN[j] = g_srccsr[t + 8 + j];
        }
        if (n + 1 < nb) { CP_WAIT(1); } else { CP_WAIT(0); }
        __syncwarp();

        uint32_t stg = wbase + (n & 1) * 4096;
        float part[4];
        #pragma unroll
        for (int j = 0; j < 4; j++) {
            float4 A = __ldg(&g_eacsr[t + j]);
            sea0 += A.x; sea1 += A.y; sea2 += A.z;
            float4 va, vb;
            asm volatile("ld.shared.v4.f32 {%0,%1,%2,%3}, [%4];"
                         : "=f"(va.x), "=f"(va.y), "=f"(va.z), "=f"(va.w)
                         : "r"(stg + j * 1024 + swz));
            asm volatile("ld.shared.v4.f32 {%0,%1,%2,%3}, [%4];"
                         : "=f"(vb.x), "=f"(vb.y), "=f"(vb.z), "=f"(vb.w)
                         : "r"(stg + j * 1024 + (swz ^ 16)));
            float xv[8] = {va.x, va.y, va.z, va.w, vb.x, vb.y, vb.z, vb.w};
            float p = 0.f;
            #pragma unroll
            for (int i = 0; i < 8; i++) {
                float m = xv[i] + xrv[i] + A.x * we0[i] + A.y * we1[i] + A.z * we2[i];
                m = (m > 0.f) ? m : 0.2f * m;
                p += m * attv[i];
            }
            part[j] = p;
        }
        #pragma unroll
        for (int o = 1; o <= 4; o <<= 1) {
            #pragma unroll
            for (int j = 0; j < 4; j++)
                part[j] += __shfl_xor_sync(0xffffffff, part[j], o);
        }

        float nm = fmaxf(fmaxf(part[0], part[1]), fmaxf(part[2], part[3]));
        nm = fmaxf(nm, mx);
        float sc = __expf(mx - nm);
        float w[4];
        #pragma unroll
        for (int j = 0; j < 4; j++) w[j] = __expf(part[j] - nm);
        den = den * sc + ((w[0] + w[1]) + (w[2] + w[3]));
        #pragma unroll
        for (int i = 0; i < 8; i++) acc[i] *= sc;
        #pragma unroll
        for (int j = 0; j < 4; j++) {
            float4 va, vb;
            asm volatile("ld.shared.v4.f32 {%0,%1,%2,%3}, [%4];"
                         : "=f"(va.x), "=f"(va.y), "=f"(va.z), "=f"(va.w)
                         : "r"(stg + j * 1024 + swz));
            asm volatile("ld.shared.v4.f32 {%0,%1,%2,%3}, [%4];"
                         : "=f"(vb.x), "=f"(vb.y), "=f"(vb.z), "=f"(vb.w)
                         : "r"(stg + j * 1024 + (swz ^ 16)));
            acc[0] += w[j] * va.x; acc[1] += w[j] * va.y;
            acc[2] += w[j] * va.z; acc[3] += w[j] * va.w;
            acc[4] += w[j] * vb.x; acc[5] += w[j] * vb.y;
            acc[6] += w[j] * vb.z; acc[7] += w[j] * vb.w;
        }
        mx = nm;

        if (hasN2) issue(n + 2, sN);   // overwrites stage (n&1) — reads above already done
    }

    // tail edges (<4), direct LDG
    for (int t = e0 + nb * 4; t < e1; t++) {
        int sA = g_srccsr[t];
        float4 A = __ldg(&g_eacsr[t]);
        sea0 += A.x; sea1 += A.y; sea2 += A.z;
        const float4* p = (const float4*)(xl + (size_t)sA * HC + jbase);
        float4 a = __ldg(p), b = __ldg(p + 1);
        float xlv[8] = {a.x, a.y, a.z, a.w, b.x, b.y, b.z, b.w};
        update1(xlv, A.x, A.y, A.z);
    }

    // self loop (edge_attr = mean of incoming)
    {
        float inv = 1.f / fmaxf((float)deg, 1.f);
        const float4* p = (const float4*)(xl + (size_t)node * HC + jbase);
        float4 a = __ldg(p), b = __ldg(p + 1);
        float xlv[8] = {a.x, a.y, a.z, a.w, b.x, b.y, b.z, b.w};
        update1(xlv, sea0 * inv, sea1 * inv, sea2 * inv);
    }

    float inv = 1.f / den;
    #pragma unroll
    for (int i = 0; i < 8; i++) {
        float r = acc[i] * inv;
        r += __shfl_xor_sync(0xffffffff, r, 8);
        r += __shfl_xor_sync(0xffffffff, r, 16);
        acc[i] = r * 0.25f;
    }
    if (lane < 8) {
        #pragma unroll
        for (int i = 0; i < 8; i++) {
            int c = jbase + i;
            out[(size_t)node * CC + c] = fmaxf(acc[i] + bias[c], 0.f);
        }
    }
}

// ---------------- final projection ------------------------------------------
__global__ __launch_bounds__(256)
void mu_kernel(const float* __restrict__ h, const float* __restrict__ Wmu,
               const float* __restrict__ bmu, float* __restrict__ out) {
    __shared__ float sW[CC * LAT];
    __shared__ float sb[LAT];
    int tid = threadIdx.x;
    for (int i = tid; i < CC * LAT; i += 256) sW[i] = Wmu[i];
    if (tid < LAT) sb[tid] = bmu[tid];
    __syncthreads();
    int warp = tid >> 5, lane = tid & 31;
    int node = blockIdx.x * 8 + warp;
    if (node >= NN) return;
    const float* hr = h + (size_t)node * CC;
    float sum = sb[lane];
    #pragma unroll
    for (int c = 0; c < CC; c++)
        sum += hr[c] * sW[c * LAT + lane];
    out[(size_t)node * LAT + lane] = sum;
}

// ---------------- host launcher ---------------------------------------------
extern "C" void kernel_launch(void* const* d_in, const int* in_sizes, int n_in,
                              void* d_out, int out_size) {
    const float* x   = (const float*)d_in[0];
    const int*   ei  = (const int*)  d_in[1];
    const float* ea  = (const float*)d_in[2];
    const float* Wl0 = (const float*)d_in[3];
    const float* bl0 = (const float*)d_in[4];
    const float* Wr0 = (const float*)d_in[5];
    const float* br0 = (const float*)d_in[6];
    const float* We0 = (const float*)d_in[7];
    const float* at0 = (const float*)d_in[8];
    const float* bi0 = (const float*)d_in[9];
    const float* Wl1 = (const float*)d_in[10];
    const float* bl1 = (const float*)d_in[11];
    const float* Wr1 = (const float*)d_in[12];
    const float* br1 = (const float*)d_in[13];
    const float* We1 = (const float*)d_in[14];
    const float* at1 = (const float*)d_in[15];
    const float* bi1 = (const float*)d_in[16];
    const float* Wmu = (const float*)d_in[17];
    const float* bmu = (const float*)d_in[18];
    float* out = (float*)d_out;

    const int* src = ei;
    const int* dst = ei + EE;

    float* xl; cudaGetSymbolAddress((void**)&xl, g_xl);
    float* xr; cudaGetSymbolAddress((void**)&xr, g_xr);
    float* h ; cudaGetSymbolAddress((void**)&h , g_h );
    uint32_t* aph; cudaGetSymbolAddress((void**)&aph, g_aph);
    uint32_t* apl; cudaGetSymbolAddress((void**)&apl, g_apl);
    uint32_t* wph; cudaGetSymbolAddress((void**)&wph, g_wph);
    uint32_t* wpl; cudaGetSymbolAddress((void**)&wpl, g_wpl);

    cudaFuncSetAttribute(gemm_fused_kernel, cudaFuncAttributeMaxDynamicSharedMemorySize, 98304);

    const int SCAN_BLOCKS = (NN + 1023) / 1024;
    dim3 gemm_grid(MT, 4);
    dim3 agg_grid((NN + 3) / 4);

    init_kernel<<<(NN + 255) / 256, 256>>>();
    convertA_kernel<<<(MT * 16 * 256 + 255) / 256, 256>>>(x, 256, 16);
    convertW_kernel<<<65536 / 256, 256>>>(Wl0, Wr0, Wl1, Wr1);

    gemm_fused_kernel<<<gemm_grid, 256, 98304>>>(aph, apl,
        wph + 0 * 32768, wpl + 0 * 32768, wph + 1 * 32768, wpl + 1 * 32768,
        bl0, br0, xl, xr, 16);

    edge_deg_kernel<<<(EE + 255) / 256, 256>>>(dst);
    deg_blocksum_kernel<<<SCAN_BLOCKS, 1024>>>();
    bsum_scan_kernel<<<1, 1>>>(SCAN_BLOCKS);
    off_write_kernel<<<SCAN_BLOCKS, 1024>>>();
    csr_fill_kernel<<<(EE + 255) / 256, 256>>>(src, dst, ea);

    gat_agg_kernel<<<agg_grid, 128>>>(xl, xr, We0, at0, bi0, h);

    convertA_kernel<<<(MT * 4 * 256 + 255) / 256, 256>>>(h, 64, 4);
    gemm_fused_kernel<<<gemm_grid, 256, 98304>>>(aph, apl,
        wph + 2 * 32768, wpl + 2 * 32768, wph + 3 * 32768, wpl + 3 * 32768,
        bl1, br1, xl, xr, 4);

    gat_agg_kernel<<<agg_grid, 128>>>(xl, xr, We1, at1, bi1, h);

    mu_kernel<<<(NN + 7) / 8, 256>>>(h, Wmu, bmu, out);
}